// round 2
// baseline (speedup 1.0000x reference)
#include <cuda_runtime.h>

#define NS 128          // samples per ray
#define NH 64           // hidden units
#define THREADS 128

__global__ __launch_bounds__(THREADS)
void nerf_render_kernel(
    const float* __restrict__ rays_o, const float* __restrict__ rays_d,
    const float* __restrict__ W1, const float* __restrict__ W2,
    const float* __restrict__ b1, const float* __restrict__ w_sigma,
    const float* __restrict__ W_color,
    float* __restrict__ out_image, float* __restrict__ out_depth,
    float* __restrict__ out_weights, float* __restrict__ out_wsum)
{
    __shared__ float4 sW1[3][NH/4];    // W1[c][j]
    __shared__ float4 sDWB[NH/4];      // d·W2 + b1
    __shared__ float4 sWS[NH/4];       // w_sigma
    __shared__ float4 sWC[3][NH/4];    // W_color transposed to [c][j]
    __shared__ float sScan[4];
    __shared__ float sRed[5][4];

    const int r    = blockIdx.x;
    const int tid  = threadIdx.x;
    const int lane = tid & 31;
    const int wid  = tid >> 5;

    // ---- stage weights in shared (192 elements > 128 threads: strided!) ----
    float* w1f = (float*)sW1;
    float* wcf = (float*)sWC;
    #pragma unroll
    for (int i = tid; i < 3*NH; i += THREADS) {
        w1f[i] = W1[i];                                   // [3][64] row-major
        const int j = i / 3, c = i - 3*j;                 // W_color is [64][3]
        wcf[c*NH + j] = W_color[i];                       // -> transposed [3][64]
    }
    if (tid < NH) ((float*)sWS)[tid] = w_sigma[tid];

    // ---- per-ray data (broadcast loads, L1-cached) ----
    const float ox = rays_o[r*3+0], oy = rays_o[r*3+1], oz = rays_o[r*3+2];
    const float dx = rays_d[r*3+0], dy = rays_d[r*3+1], dz = rays_d[r*3+2];

    if (tid < NH)
        ((float*)sDWB)[tid] = b1[tid] + dx*W2[tid] + dy*W2[NH+tid] + dz*W2[2*NH+tid];

    // ---- near/far via cube AABB (replicates reference exactly) ----
    float near_t, far_t;
    {
        const float ivx = 1.0f/(dx + 1e-15f);
        const float ivy = 1.0f/(dy + 1e-15f);
        const float ivz = 1.0f/(dz + 1e-15f);
        const float t1x = (-1.0f - ox)*ivx, t2x = (1.0f - ox)*ivx;
        const float t1y = (-1.0f - oy)*ivy, t2y = (1.0f - oy)*ivy;
        const float t1z = (-1.0f - oz)*ivz, t2z = (1.0f - oz)*ivz;
        near_t = fmaxf(fmaxf(fminf(t1x,t2x), fminf(t1y,t2y)), fminf(t1z,t2z));
        far_t  = fminf(fminf(fmaxf(t1x,t2x), fmaxf(t1y,t2y)), fmaxf(t1z,t2z));
        if (far_t < near_t) { near_t = 1e9f; far_t = 1e9f; }   // miss
        near_t = fmaxf(near_t, 0.05f);                          // MIN_NEAR
    }
    const float span  = far_t - near_t;
    const float delta = span * (1.0f/(NS-1));
    const float zval  = near_t + span * ((float)tid * (1.0f/(NS-1)));

    // sample point, clamped to AABB
    const float px = fminf(fmaxf(ox + dx*zval, -1.0f), 1.0f);
    const float py = fminf(fmaxf(oy + dy*zval, -1.0f), 1.0f);
    const float pz = fminf(fmaxf(oz + dz*zval, -1.0f), 1.0f);

    __syncthreads();

    // ---- tiny MLP: h = relu(p·W1 + dW2b); project to sigma + rgb ----
    float sacc = 0.0f, c0 = 0.0f, c1 = 0.0f, c2 = 0.0f;
    #pragma unroll
    for (int q = 0; q < NH/4; ++q) {
        const float4 ax = sW1[0][q], ay = sW1[1][q], az = sW1[2][q];
        const float4 db = sDWB[q],   ws = sWS[q];
        const float4 u0 = sWC[0][q], u1 = sWC[1][q], u2 = sWC[2][q];
        float h;
        h = fmaxf(fmaf(pz, az.x, fmaf(py, ay.x, fmaf(px, ax.x, db.x))), 0.0f);
        sacc = fmaf(h, ws.x, sacc); c0 = fmaf(h, u0.x, c0); c1 = fmaf(h, u1.x, c1); c2 = fmaf(h, u2.x, c2);
        h = fmaxf(fmaf(pz, az.y, fmaf(py, ay.y, fmaf(px, ax.y, db.y))), 0.0f);
        sacc = fmaf(h, ws.y, sacc); c0 = fmaf(h, u0.y, c0); c1 = fmaf(h, u1.y, c1); c2 = fmaf(h, u2.y, c2);
        h = fmaxf(fmaf(pz, az.z, fmaf(py, ay.z, fmaf(px, ax.z, db.z))), 0.0f);
        sacc = fmaf(h, ws.z, sacc); c0 = fmaf(h, u0.z, c0); c1 = fmaf(h, u1.z, c1); c2 = fmaf(h, u2.z, c2);
        h = fmaxf(fmaf(pz, az.w, fmaf(py, ay.w, fmaf(px, ax.w, db.w))), 0.0f);
        sacc = fmaf(h, ws.w, sacc); c0 = fmaf(h, u0.w, c0); c1 = fmaf(h, u1.w, c1); c2 = fmaf(h, u2.w, c2);
    }

    // activations (stable softplus; fast sigmoid)
    const float sigma = fmaxf(sacc, 0.0f) + log1pf(__expf(-fabsf(sacc)));
    const float rr = 1.0f / (1.0f + __expf(-c0));
    const float rg = 1.0f / (1.0f + __expf(-c1));
    const float rb = 1.0f / (1.0f + __expf(-c2));

    const float e     = __expf(-delta * sigma);
    const float alpha = 1.0f - e;
    const float v     = (1.0f - alpha) + 1e-15f;   // matches reference rounding path

    // ---- exclusive multiplicative scan over samples (transmittance T) ----
    float p = v;
    #pragma unroll
    for (int off = 1; off < 32; off <<= 1) {
        const float n = __shfl_up_sync(0xffffffffu, p, off);
        if (lane >= off) p *= n;
    }
    if (lane == 31) sScan[wid] = p;   // warp total (inclusive)
    __syncthreads();
    float prefix = 1.0f;
    #pragma unroll
    for (int w = 0; w < 4; ++w)
        if (w < wid) prefix *= sScan[w];
    float excl = __shfl_up_sync(0xffffffffu, p, 1);
    if (lane == 0) excl = 1.0f;
    const float T  = prefix * excl;
    const float wt = alpha * T;

    // ---- outputs ----
    out_weights[r * NS + tid] = wt;

    float s0 = wt;           // weights_sum
    float s1 = wt * zval;    // depth
    float s2 = wt * rr, s3 = wt * rg, s4 = wt * rb;   // image
    #pragma unroll
    for (int off = 16; off; off >>= 1) {
        s0 += __shfl_xor_sync(0xffffffffu, s0, off);
        s1 += __shfl_xor_sync(0xffffffffu, s1, off);
        s2 += __shfl_xor_sync(0xffffffffu, s2, off);
        s3 += __shfl_xor_sync(0xffffffffu, s3, off);
        s4 += __shfl_xor_sync(0xffffffffu, s4, off);
    }
    if (lane == 0) {
        sRed[0][wid] = s0; sRed[1][wid] = s1;
        sRed[2][wid] = s2; sRed[3][wid] = s3; sRed[4][wid] = s4;
    }
    __syncthreads();
    if (tid == 0) {
        float t0 = sRed[0][0] + sRed[0][1] + sRed[0][2] + sRed[0][3];
        float t1 = sRed[1][0] + sRed[1][1] + sRed[1][2] + sRed[1][3];
        float t2 = sRed[2][0] + sRed[2][1] + sRed[2][2] + sRed[2][3];
        float t3 = sRed[3][0] + sRed[3][1] + sRed[3][2] + sRed[3][3];
        float t4 = sRed[4][0] + sRed[4][1] + sRed[4][2] + sRed[4][3];
        out_wsum[r]      = t0;
        out_depth[r]     = t1;
        out_image[r*3+0] = t2;
        out_image[r*3+1] = t3;
        out_image[r*3+2] = t4;
    }
}

extern "C" void kernel_launch(void* const* d_in, const int* in_sizes, int n_in,
                              void* d_out, int out_size) {
    const float* rays_o  = (const float*)d_in[0];
    const float* rays_d  = (const float*)d_in[1];
    const float* W1      = (const float*)d_in[2];
    const float* W2      = (const float*)d_in[3];
    const float* b1      = (const float*)d_in[4];
    const float* w_sigma = (const float*)d_in[5];
    const float* W_color = (const float*)d_in[6];

    const int BN = in_sizes[0] / 3;   // B*N rays

    float* out = (float*)d_out;
    // output layout: image [BN,3], depth [BN], weights [BN,NS], weights_sum [BN]
    float* out_image   = out;
    float* out_depth   = out + (size_t)BN * 3;
    float* out_weights = out + (size_t)BN * 4;
    float* out_wsum    = out + (size_t)BN * 4 + (size_t)BN * NS;

    nerf_render_kernel<<<BN, THREADS>>>(rays_o, rays_d, W1, W2, b1, w_sigma,
                                        W_color, out_image, out_depth,
                                        out_weights, out_wsum);
}

// round 3
// speedup vs baseline: 1.4873x; 1.4873x over previous
#include <cuda_runtime.h>

#define NS   128         // samples per ray
#define NH   64          // hidden units
#define RPB  4           // rays per block (one warp per ray)
#define THREADS 128

__global__ __launch_bounds__(THREADS)
void nerf_render_kernel(
    const float* __restrict__ rays_o, const float* __restrict__ rays_d,
    const float* __restrict__ W1, const float* __restrict__ W2,
    const float* __restrict__ b1, const float* __restrict__ w_sigma,
    const float* __restrict__ W_color,
    float* __restrict__ out_image, float* __restrict__ out_depth,
    float* __restrict__ out_weights, float* __restrict__ out_wsum,
    const int BN)
{
    __shared__ float4 sW1[3][NH/4];     // W1[c][j]
    __shared__ float4 sWS[NH/4];        // w_sigma
    __shared__ float4 sWC[3][NH/4];     // W_color transposed to [c][j]
    __shared__ float4 sDWB[RPB][NH/4];  // per-ray d·W2 + b1

    const int tid  = threadIdx.x;
    const int lane = tid & 31;
    const int wid  = tid >> 5;
    const int r    = blockIdx.x * RPB + wid;
    const bool active = (r < BN);

    // ---- stage shared weights (192 elems, strided over 128 threads) ----
    float* w1f = (float*)sW1;
    float* wcf = (float*)sWC;
    #pragma unroll
    for (int i = tid; i < 3*NH; i += THREADS) {
        w1f[i] = W1[i];                       // [3][64] row-major
        const int j = i / 3, c = i - 3*j;     // W_color is [64][3]
        wcf[c*NH + j] = W_color[i];           // -> [3][64]
    }
    if (tid < NH) ((float*)sWS)[tid] = w_sigma[tid];

    // ---- per-ray data (all lanes of a warp share one ray) ----
    float ox=0.f, oy=0.f, oz=0.f, dx=1.f, dy=1.f, dz=1.f;
    if (active) {
        ox = rays_o[r*3+0]; oy = rays_o[r*3+1]; oz = rays_o[r*3+2];
        dx = rays_d[r*3+0]; dy = rays_d[r*3+1]; dz = rays_d[r*3+2];
    }

    // per-ray d·W2 + b1 into this warp's shared slot (2 entries per lane)
    {
        float* dwb = (float*)sDWB[wid];
        #pragma unroll
        for (int j = lane; j < NH; j += 32)
            dwb[j] = b1[j] + dx*W2[j] + dy*W2[NH+j] + dz*W2[2*NH+j];
    }
    __syncthreads();

    // ---- near/far via cube AABB (replicates reference exactly) ----
    float near_t, far_t;
    {
        const float ivx = 1.0f/(dx + 1e-15f);
        const float ivy = 1.0f/(dy + 1e-15f);
        const float ivz = 1.0f/(dz + 1e-15f);
        const float t1x = (-1.0f - ox)*ivx, t2x = (1.0f - ox)*ivx;
        const float t1y = (-1.0f - oy)*ivy, t2y = (1.0f - oy)*ivy;
        const float t1z = (-1.0f - oz)*ivz, t2z = (1.0f - oz)*ivz;
        near_t = fmaxf(fmaxf(fminf(t1x,t2x), fminf(t1y,t2y)), fminf(t1z,t2z));
        far_t  = fminf(fminf(fmaxf(t1x,t2x), fmaxf(t1y,t2y)), fmaxf(t1z,t2z));
        if (far_t < near_t) { near_t = 1e9f; far_t = 1e9f; }   // miss
        near_t = fmaxf(near_t, 0.05f);                          // MIN_NEAR
    }
    const float span  = far_t - near_t;
    const float delta = span * (1.0f/(NS-1));

    // ---- 4 contiguous samples per lane: s = 4*lane + k ----
    float zv[4], px[4], py[4], pz[4];
    #pragma unroll
    for (int k = 0; k < 4; ++k) {
        const int s = 4*lane + k;
        zv[k] = near_t + span * ((float)s * (1.0f/(NS-1)));
        px[k] = fminf(fmaxf(ox + dx*zv[k], -1.0f), 1.0f);
        py[k] = fminf(fmaxf(oy + dy*zv[k], -1.0f), 1.0f);
        pz[k] = fminf(fmaxf(oz + dz*zv[k], -1.0f), 1.0f);
    }

    // ---- tiny MLP for 4 samples, weights loaded once per 4 units ----
    float sacc[4] = {0,0,0,0}, cc0[4] = {0,0,0,0},
          cc1[4] = {0,0,0,0}, cc2[4] = {0,0,0,0};

    #define DO_UNIT(C)                                                        \
    {                                                                         \
        const float a0 = ax.C, a1 = ay.C, a2 = az.C, bb = db.C;               \
        const float w  = ws.C, q0 = u0.C, q1 = u1.C, q2 = u2.C;               \
        _Pragma("unroll")                                                     \
        for (int s = 0; s < 4; ++s) {                                         \
            const float h = fmaxf(                                            \
                fmaf(pz[s], a2, fmaf(py[s], a1, fmaf(px[s], a0, bb))), 0.0f); \
            sacc[s] = fmaf(h, w,  sacc[s]);                                   \
            cc0[s]  = fmaf(h, q0, cc0[s]);                                    \
            cc1[s]  = fmaf(h, q1, cc1[s]);                                    \
            cc2[s]  = fmaf(h, q2, cc2[s]);                                    \
        }                                                                     \
    }

    #pragma unroll 4
    for (int q = 0; q < NH/4; ++q) {
        const float4 ax = sW1[0][q], ay = sW1[1][q], az = sW1[2][q];
        const float4 db = sDWB[wid][q], ws = sWS[q];
        const float4 u0 = sWC[0][q], u1 = sWC[1][q], u2 = sWC[2][q];
        DO_UNIT(x) DO_UNIT(y) DO_UNIT(z) DO_UNIT(w)
    }
    #undef DO_UNIT

    // ---- activations + alpha per sample ----
    float alpha[4], v[4], rr[4], rg[4], rb[4];
    #pragma unroll
    for (int k = 0; k < 4; ++k) {
        const float sig = fmaxf(sacc[k], 0.0f) + log1pf(__expf(-fabsf(sacc[k])));
        rr[k] = 1.0f / (1.0f + __expf(-cc0[k]));
        rg[k] = 1.0f / (1.0f + __expf(-cc1[k]));
        rb[k] = 1.0f / (1.0f + __expf(-cc2[k]));
        alpha[k] = 1.0f - __expf(-delta * sig);
        v[k]     = (1.0f - alpha[k]) + 1e-15f;
    }

    // ---- exclusive multiplicative scan over 128 samples (warp-local) ----
    // local inclusive products
    const float l0 = v[0];
    const float l1 = l0 * v[1];
    const float l2 = l1 * v[2];
    const float l3 = l2 * v[3];
    // warp inclusive scan of per-lane totals
    float p = l3;
    #pragma unroll
    for (int off = 1; off < 32; off <<= 1) {
        const float n = __shfl_up_sync(0xffffffffu, p, off);
        if (lane >= off) p *= n;
    }
    float excl = __shfl_up_sync(0xffffffffu, p, 1);
    if (lane == 0) excl = 1.0f;
    // transmittance per sample, weight per sample
    float wt[4];
    wt[0] = alpha[0] * excl;
    wt[1] = alpha[1] * (excl * l0);
    wt[2] = alpha[2] * (excl * l1);
    wt[3] = alpha[3] * (excl * l2);

    // ---- outputs ----
    if (active) {
        float4 wv = make_float4(wt[0], wt[1], wt[2], wt[3]);
        *(float4*)(out_weights + (size_t)r * NS + 4*lane) = wv;
    }

    float s0 = 0.f, s1 = 0.f, s2 = 0.f, s3 = 0.f, s4 = 0.f;
    #pragma unroll
    for (int k = 0; k < 4; ++k) {
        s0 += wt[k];
        s1 += wt[k] * zv[k];
        s2 += wt[k] * rr[k];
        s3 += wt[k] * rg[k];
        s4 += wt[k] * rb[k];
    }
    #pragma unroll
    for (int off = 16; off; off >>= 1) {
        s0 += __shfl_xor_sync(0xffffffffu, s0, off);
        s1 += __shfl_xor_sync(0xffffffffu, s1, off);
        s2 += __shfl_xor_sync(0xffffffffu, s2, off);
        s3 += __shfl_xor_sync(0xffffffffu, s3, off);
        s4 += __shfl_xor_sync(0xffffffffu, s4, off);
    }
    if (active && lane == 0) {
        out_wsum[r]      = s0;
        out_depth[r]     = s1;
        out_image[r*3+0] = s2;
        out_image[r*3+1] = s3;
        out_image[r*3+2] = s4;
    }
}

extern "C" void kernel_launch(void* const* d_in, const int* in_sizes, int n_in,
                              void* d_out, int out_size) {
    const float* rays_o  = (const float*)d_in[0];
    const float* rays_d  = (const float*)d_in[1];
    const float* W1      = (const float*)d_in[2];
    const float* W2      = (const float*)d_in[3];
    const float* b1      = (const float*)d_in[4];
    const float* w_sigma = (const float*)d_in[5];
    const float* W_color = (const float*)d_in[6];

    const int BN = in_sizes[0] / 3;   // B*N rays

    float* out = (float*)d_out;
    // output layout: image [BN,3], depth [BN], weights [BN,NS], weights_sum [BN]
    float* out_image   = out;
    float* out_depth   = out + (size_t)BN * 3;
    float* out_weights = out + (size_t)BN * 4;
    float* out_wsum    = out + (size_t)BN * 4 + (size_t)BN * NS;

    const int blocks = (BN + RPB - 1) / RPB;
    nerf_render_kernel<<<blocks, THREADS>>>(rays_o, rays_d, W1, W2, b1, w_sigma,
                                            W_color, out_image, out_depth,
                                            out_weights, out_wsum, BN);
}

// round 4
// speedup vs baseline: 1.8088x; 1.2162x over previous
#include <cuda_runtime.h>

#define NS   128         // samples per ray
#define NH   64          // hidden units
#define RPB  4           // rays per block (one warp per ray)
#define THREADS 128

typedef unsigned long long u64;

__device__ __forceinline__ u64 ffma2(u64 a, u64 b, u64 c) {
    u64 d;
    asm("fma.rn.f32x2 %0, %1, %2, %3;" : "=l"(d) : "l"(a), "l"(b), "l"(c));
    return d;
}
__device__ __forceinline__ u64 pack2(float lo, float hi) {
    u64 r;
    asm("mov.b64 %0, {%1, %2};" : "=l"(r) : "f"(lo), "f"(hi));
    return r;
}
__device__ __forceinline__ u64 relu2(u64 x) {
    float lo, hi;
    asm("mov.b64 {%0, %1}, %2;" : "=f"(lo), "=f"(hi) : "l"(x));
    lo = fmaxf(lo, 0.0f);
    hi = fmaxf(hi, 0.0f);
    return pack2(lo, hi);
}
__device__ __forceinline__ float lo2(u64 x) {
    float lo, hi;
    asm("mov.b64 {%0, %1}, %2;" : "=f"(lo), "=f"(hi) : "l"(x));
    return lo;
}
__device__ __forceinline__ float hi2(u64 x) {
    float lo, hi;
    asm("mov.b64 {%0, %1}, %2;" : "=f"(lo), "=f"(hi) : "l"(x));
    return hi;
}

union F4U { float4 f; u64 q[2]; };

__global__ __launch_bounds__(THREADS)
void nerf_render_kernel(
    const float* __restrict__ rays_o, const float* __restrict__ rays_d,
    const float* __restrict__ W1, const float* __restrict__ W2,
    const float* __restrict__ b1, const float* __restrict__ w_sigma,
    const float* __restrict__ W_color,
    float* __restrict__ out_image, float* __restrict__ out_depth,
    float* __restrict__ out_weights, float* __restrict__ out_wsum,
    const int BN)
{
    // All weights stored DUPLICATED: float2{w,w} per unit -> float4 covers 2 units.
    __shared__ float4 sWS4[NH/2];           // w_sigma dup
    __shared__ float4 sU04[NH/2];           // W_color[:,0] dup
    __shared__ float4 sU14[NH/2];           // W_color[:,1] dup
    __shared__ float4 sU24[NH/2];           // W_color[:,2] dup
    __shared__ float4 sBase4[RPB][NH/2];    // per-ray base dup
    __shared__ float4 sSlope4[RPB][NH/2];   // per-ray slope dup

    const int tid  = threadIdx.x;
    const int lane = tid & 31;
    const int wid  = tid >> 5;
    const int r    = blockIdx.x * RPB + wid;
    const bool active = (r < BN);

    // ---- stage ray-independent weights (dup'd), one unit per thread<64 ----
    if (tid < NH) {
        const float w  = w_sigma[tid];
        const float c0 = W_color[tid*3+0];
        const float c1 = W_color[tid*3+1];
        const float c2 = W_color[tid*3+2];
        ((float2*)sWS4)[tid] = make_float2(w,  w);
        ((float2*)sU04)[tid] = make_float2(c0, c0);
        ((float2*)sU14)[tid] = make_float2(c1, c1);
        ((float2*)sU24)[tid] = make_float2(c2, c2);
    }

    // ---- per-ray data (all lanes of a warp share one ray) ----
    float ox=0.f, oy=0.f, oz=0.f, dx=1.f, dy=1.f, dz=1.f;
    if (active) {
        ox = rays_o[r*3+0]; oy = rays_o[r*3+1]; oz = rays_o[r*3+2];
        dx = rays_d[r*3+0]; dy = rays_d[r*3+1]; dz = rays_d[r*3+2];
    }

    // ---- per-ray base/slope per hidden unit (2 units per lane), dup'd ----
    {
        float2* bp = (float2*)sBase4[wid];
        float2* sp = (float2*)sSlope4[wid];
        #pragma unroll
        for (int j = lane; j < NH; j += 32) {
            const float a0 = W1[j], a1 = W1[NH+j], a2 = W1[2*NH+j];
            const float sl = dx*a0 + dy*a1 + dz*a2;
            const float bs = ox*a0 + oy*a1 + oz*a2
                           + b1[j] + dx*W2[j] + dy*W2[NH+j] + dz*W2[2*NH+j];
            bp[j] = make_float2(bs, bs);
            sp[j] = make_float2(sl, sl);
        }
    }
    __syncthreads();

    // ---- near/far via cube AABB (replicates reference exactly) ----
    float near_t, far_t;
    {
        const float ivx = 1.0f/(dx + 1e-15f);
        const float ivy = 1.0f/(dy + 1e-15f);
        const float ivz = 1.0f/(dz + 1e-15f);
        const float t1x = (-1.0f - ox)*ivx, t2x = (1.0f - ox)*ivx;
        const float t1y = (-1.0f - oy)*ivy, t2y = (1.0f - oy)*ivy;
        const float t1z = (-1.0f - oz)*ivz, t2z = (1.0f - oz)*ivz;
        near_t = fmaxf(fmaxf(fminf(t1x,t2x), fminf(t1y,t2y)), fminf(t1z,t2z));
        far_t  = fminf(fminf(fmaxf(t1x,t2x), fmaxf(t1y,t2y)), fmaxf(t1z,t2z));
        if (far_t < near_t) { near_t = 1e9f; far_t = 1e9f; }   // miss
        near_t = fmaxf(near_t, 0.05f);                          // MIN_NEAR
    }
    const float span  = far_t - near_t;
    const float delta = span * (1.0f/(NS-1));

    // ---- 4 contiguous samples per lane: s = 4*lane + k ----
    float zv[4];
    #pragma unroll
    for (int k = 0; k < 4; ++k) {
        const int s = 4*lane + k;
        zv[k] = near_t + span * ((float)s * (1.0f/(NS-1)));
    }
    const u64 zp0 = pack2(zv[0], zv[1]);
    const u64 zp1 = pack2(zv[2], zv[3]);

    // ---- MLP over 64 units, packed f32x2, 2 units per iteration ----
    u64 as0 = 0ull, as1 = 0ull;   // sigma accum (pairs 01, 23)
    u64 ar0 = 0ull, ar1 = 0ull;   // color r
    u64 ag0 = 0ull, ag1 = 0ull;   // color g
    u64 ab0 = 0ull, ab1 = 0ull;   // color b

    #pragma unroll 8
    for (int u = 0; u < NH/2; ++u) {
        F4U bs, sl, ws, q0, q1, q2;
        bs.f = sBase4[wid][u];
        sl.f = sSlope4[wid][u];
        ws.f = sWS4[u];
        q0.f = sU04[u];
        q1.f = sU14[u];
        q2.f = sU24[u];
        #pragma unroll
        for (int h = 0; h < 2; ++h) {           // two units in this float4
            const u64 B = bs.q[h], S = sl.q[h];
            const u64 h0 = relu2(ffma2(zp0, S, B));
            const u64 h1 = relu2(ffma2(zp1, S, B));
            as0 = ffma2(h0, ws.q[h], as0);  as1 = ffma2(h1, ws.q[h], as1);
            ar0 = ffma2(h0, q0.q[h], ar0);  ar1 = ffma2(h1, q0.q[h], ar1);
            ag0 = ffma2(h0, q1.q[h], ag0);  ag1 = ffma2(h1, q1.q[h], ag1);
            ab0 = ffma2(h0, q2.q[h], ab0);  ab1 = ffma2(h1, q2.q[h], ab1);
        }
    }

    float sacc[4] = { lo2(as0), hi2(as0), lo2(as1), hi2(as1) };
    float cc0[4]  = { lo2(ar0), hi2(ar0), lo2(ar1), hi2(ar1) };
    float cc1[4]  = { lo2(ag0), hi2(ag0), lo2(ag1), hi2(ag1) };
    float cc2[4]  = { lo2(ab0), hi2(ab0), lo2(ab1), hi2(ab1) };

    // ---- activations + alpha per sample ----
    float alpha[4], v[4], rr[4], rg[4], rb[4];
    #pragma unroll
    for (int k = 0; k < 4; ++k) {
        const float sig = fmaxf(sacc[k], 0.0f) + log1pf(__expf(-fabsf(sacc[k])));
        rr[k] = 1.0f / (1.0f + __expf(-cc0[k]));
        rg[k] = 1.0f / (1.0f + __expf(-cc1[k]));
        rb[k] = 1.0f / (1.0f + __expf(-cc2[k]));
        alpha[k] = 1.0f - __expf(-delta * sig);
        v[k]     = (1.0f - alpha[k]) + 1e-15f;
    }

    // ---- exclusive multiplicative scan over 128 samples (warp-local) ----
    const float l0 = v[0];
    const float l1 = l0 * v[1];
    const float l2 = l1 * v[2];
    const float l3 = l2 * v[3];
    float p = l3;
    #pragma unroll
    for (int off = 1; off < 32; off <<= 1) {
        const float n = __shfl_up_sync(0xffffffffu, p, off);
        if (lane >= off) p *= n;
    }
    float excl = __shfl_up_sync(0xffffffffu, p, 1);
    if (lane == 0) excl = 1.0f;
    float wt[4];
    wt[0] = alpha[0] * excl;
    wt[1] = alpha[1] * (excl * l0);
    wt[2] = alpha[2] * (excl * l1);
    wt[3] = alpha[3] * (excl * l2);

    // ---- outputs ----
    if (active) {
        float4 wv = make_float4(wt[0], wt[1], wt[2], wt[3]);
        *(float4*)(out_weights + (size_t)r * NS + 4*lane) = wv;
    }

    float s0 = 0.f, s1 = 0.f, s2 = 0.f, s3 = 0.f, s4 = 0.f;
    #pragma unroll
    for (int k = 0; k < 4; ++k) {
        s0 += wt[k];
        s1 += wt[k] * zv[k];
        s2 += wt[k] * rr[k];
        s3 += wt[k] * rg[k];
        s4 += wt[k] * rb[k];
    }
    #pragma unroll
    for (int off = 16; off; off >>= 1) {
        s0 += __shfl_xor_sync(0xffffffffu, s0, off);
        s1 += __shfl_xor_sync(0xffffffffu, s1, off);
        s2 += __shfl_xor_sync(0xffffffffu, s2, off);
        s3 += __shfl_xor_sync(0xffffffffu, s3, off);
        s4 += __shfl_xor_sync(0xffffffffu, s4, off);
    }
    if (active && lane == 0) {
        out_wsum[r]      = s0;
        out_depth[r]     = s1;
        out_image[r*3+0] = s2;
        out_image[r*3+1] = s3;
        out_image[r*3+2] = s4;
    }
}

extern "C" void kernel_launch(void* const* d_in, const int* in_sizes, int n_in,
                              void* d_out, int out_size) {
    const float* rays_o  = (const float*)d_in[0];
    const float* rays_d  = (const float*)d_in[1];
    const float* W1      = (const float*)d_in[2];
    const float* W2      = (const float*)d_in[3];
    const float* b1      = (const float*)d_in[4];
    const float* w_sigma = (const float*)d_in[5];
    const float* W_color = (const float*)d_in[6];

    const int BN = in_sizes[0] / 3;   // B*N rays

    float* out = (float*)d_out;
    // output layout: image [BN,3], depth [BN], weights [BN,NS], weights_sum [BN]
    float* out_image   = out;
    float* out_depth   = out + (size_t)BN * 3;
    float* out_weights = out + (size_t)BN * 4;
    float* out_wsum    = out + (size_t)BN * 4 + (size_t)BN * NS;

    const int blocks = (BN + RPB - 1) / RPB;
    nerf_render_kernel<<<blocks, THREADS>>>(rays_o, rays_d, W1, W2, b1, w_sigma,
                                            W_color, out_image, out_depth,
                                            out_weights, out_wsum, BN);
}

// round 5
// speedup vs baseline: 1.9011x; 1.0510x over previous
#include <cuda_runtime.h>

#define NS   128         // samples per ray
#define NH   64          // hidden units
#define RPB  4           // rays per block (one warp per ray)
#define THREADS 128

typedef unsigned long long u64;

__device__ __forceinline__ u64 ffma2(u64 a, u64 b, u64 c) {
    u64 d;
    asm("fma.rn.f32x2 %0, %1, %2, %3;" : "=l"(d) : "l"(a), "l"(b), "l"(c));
    return d;
}
__device__ __forceinline__ u64 pack2(float lo, float hi) {
    u64 r;
    asm("mov.b64 %0, {%1, %2};" : "=l"(r) : "f"(lo), "f"(hi));
    return r;
}
__device__ __forceinline__ u64 relu2(u64 x) {
    float lo, hi;
    asm("mov.b64 {%0, %1}, %2;" : "=f"(lo), "=f"(hi) : "l"(x));
    lo = fmaxf(lo, 0.0f);
    hi = fmaxf(hi, 0.0f);
    return pack2(lo, hi);
}
__device__ __forceinline__ float sum2(u64 x) {   // lo + hi
    float lo, hi;
    asm("mov.b64 {%0, %1}, %2;" : "=f"(lo), "=f"(hi) : "l"(x));
    return lo + hi;
}

union F4U { float4 f; u64 q[2]; };

__global__ __launch_bounds__(THREADS)
void nerf_render_kernel(
    const float* __restrict__ rays_o, const float* __restrict__ rays_d,
    const float* __restrict__ W1, const float* __restrict__ W2,
    const float* __restrict__ b1, const float* __restrict__ w_sigma,
    const float* __restrict__ W_color,
    float* __restrict__ out_image, float* __restrict__ out_depth,
    float* __restrict__ out_weights, float* __restrict__ out_wsum,
    const int BN)
{
    // Natural (non-duplicated) layouts; a float4 covers 4 hidden units.
    __shared__ float4 sWS4[NH/4];           // w_sigma
    __shared__ float4 sU04[NH/4];           // W_color[:,0]
    __shared__ float4 sU14[NH/4];           // W_color[:,1]
    __shared__ float4 sU24[NH/4];           // W_color[:,2]
    __shared__ float4 sBase4[RPB][NH/4];    // per-ray: o·W1 + d·W2 + b1
    __shared__ float4 sSlope4[RPB][NH/4];   // per-ray: d·W1

    const int tid  = threadIdx.x;
    const int lane = tid & 31;
    const int wid  = tid >> 5;
    const int r    = blockIdx.x * RPB + wid;
    const bool active = (r < BN);

    // ---- stage ray-independent weights, one unit per thread<64 ----
    if (tid < NH) {
        ((float*)sWS4)[tid] = w_sigma[tid];
        ((float*)sU04)[tid] = W_color[tid*3+0];
        ((float*)sU14)[tid] = W_color[tid*3+1];
        ((float*)sU24)[tid] = W_color[tid*3+2];
    }

    // ---- per-ray data (all lanes of a warp share one ray) ----
    float ox=0.f, oy=0.f, oz=0.f, dx=1.f, dy=1.f, dz=1.f;
    if (active) {
        ox = rays_o[r*3+0]; oy = rays_o[r*3+1]; oz = rays_o[r*3+2];
        dx = rays_d[r*3+0]; dy = rays_d[r*3+1]; dz = rays_d[r*3+2];
    }

    // ---- per-ray base/slope per hidden unit (2 units per lane) ----
    {
        float* bp = (float*)sBase4[wid];
        float* sp = (float*)sSlope4[wid];
        #pragma unroll
        for (int j = lane; j < NH; j += 32) {
            const float a0 = W1[j], a1 = W1[NH+j], a2 = W1[2*NH+j];
            sp[j] = dx*a0 + dy*a1 + dz*a2;
            bp[j] = ox*a0 + oy*a1 + oz*a2
                  + b1[j] + dx*W2[j] + dy*W2[NH+j] + dz*W2[2*NH+j];
        }
    }
    __syncthreads();

    // ---- near/far via cube AABB (replicates reference exactly) ----
    float near_t, far_t;
    {
        const float ivx = 1.0f/(dx + 1e-15f);
        const float ivy = 1.0f/(dy + 1e-15f);
        const float ivz = 1.0f/(dz + 1e-15f);
        const float t1x = (-1.0f - ox)*ivx, t2x = (1.0f - ox)*ivx;
        const float t1y = (-1.0f - oy)*ivy, t2y = (1.0f - oy)*ivy;
        const float t1z = (-1.0f - oz)*ivz, t2z = (1.0f - oz)*ivz;
        near_t = fmaxf(fmaxf(fminf(t1x,t2x), fminf(t1y,t2y)), fminf(t1z,t2z));
        far_t  = fminf(fminf(fmaxf(t1x,t2x), fmaxf(t1y,t2y)), fmaxf(t1z,t2z));
        if (far_t < near_t) { near_t = 1e9f; far_t = 1e9f; }   // miss
        near_t = fmaxf(near_t, 0.05f);                          // MIN_NEAR
    }
    const float span  = far_t - near_t;
    const float delta = span * (1.0f/(NS-1));

    // ---- 4 contiguous samples per lane: s = 4*lane + k ----
    float zv[4];
    u64 zz[4];                 // {z,z} per sample (registers)
    #pragma unroll
    for (int k = 0; k < 4; ++k) {
        const int s = 4*lane + k;
        zv[k] = near_t + span * ((float)s * (1.0f/(NS-1)));
        zz[k] = pack2(zv[k], zv[k]);
    }

    // ---- MLP: pair-packed units, 4 units per float4 iteration ----
    // Accumulators hold {even-unit partial, odd-unit partial} per sample.
    u64 as[4] = {0,0,0,0};     // sigma
    u64 ar[4] = {0,0,0,0};     // color r
    u64 ag[4] = {0,0,0,0};     // color g
    u64 ab[4] = {0,0,0,0};     // color b

    #pragma unroll
    for (int u = 0; u < NH/4; ++u) {
        F4U bs, sl, ws, q0, q1, q2;
        bs.f = sBase4[wid][u];
        sl.f = sSlope4[wid][u];
        ws.f = sWS4[u];
        q0.f = sU04[u];
        q1.f = sU14[u];
        q2.f = sU24[u];
        #pragma unroll
        for (int h = 0; h < 2; ++h) {      // two unit-pairs in this float4
            const u64 B = bs.q[h], S = sl.q[h];
            #pragma unroll
            for (int k = 0; k < 4; ++k) {
                const u64 hp = relu2(ffma2(zz[k], S, B));
                as[k] = ffma2(hp, ws.q[h], as[k]);
                ar[k] = ffma2(hp, q0.q[h], ar[k]);
                ag[k] = ffma2(hp, q1.q[h], ag[k]);
                ab[k] = ffma2(hp, q2.q[h], ab[k]);
            }
        }
    }

    // ---- activations + alpha per sample ----
    float alpha[4], v[4], rr[4], rg[4], rb[4];
    #pragma unroll
    for (int k = 0; k < 4; ++k) {
        const float sacc = sum2(as[k]);
        const float sig  = fmaxf(sacc, 0.0f) + log1pf(__expf(-fabsf(sacc)));
        rr[k] = 1.0f / (1.0f + __expf(-sum2(ar[k])));
        rg[k] = 1.0f / (1.0f + __expf(-sum2(ag[k])));
        rb[k] = 1.0f / (1.0f + __expf(-sum2(ab[k])));
        alpha[k] = 1.0f - __expf(-delta * sig);
        v[k]     = (1.0f - alpha[k]) + 1e-15f;
    }

    // ---- exclusive multiplicative scan over 128 samples (warp-local) ----
    const float l0 = v[0];
    const float l1 = l0 * v[1];
    const float l2 = l1 * v[2];
    const float l3 = l2 * v[3];
    float p = l3;
    #pragma unroll
    for (int off = 1; off < 32; off <<= 1) {
        const float n = __shfl_up_sync(0xffffffffu, p, off);
        if (lane >= off) p *= n;
    }
    float excl = __shfl_up_sync(0xffffffffu, p, 1);
    if (lane == 0) excl = 1.0f;
    float wt[4];
    wt[0] = alpha[0] * excl;
    wt[1] = alpha[1] * (excl * l0);
    wt[2] = alpha[2] * (excl * l1);
    wt[3] = alpha[3] * (excl * l2);

    // ---- outputs ----
    if (active) {
        float4 wv = make_float4(wt[0], wt[1], wt[2], wt[3]);
        *(float4*)(out_weights + (size_t)r * NS + 4*lane) = wv;
    }

    float s0 = 0.f, s1 = 0.f, s2 = 0.f, s3 = 0.f, s4 = 0.f;
    #pragma unroll
    for (int k = 0; k < 4; ++k) {
        s0 += wt[k];
        s1 += wt[k] * zv[k];
        s2 += wt[k] * rr[k];
        s3 += wt[k] * rg[k];
        s4 += wt[k] * rb[k];
    }
    #pragma unroll
    for (int off = 16; off; off >>= 1) {
        s0 += __shfl_xor_sync(0xffffffffu, s0, off);
        s1 += __shfl_xor_sync(0xffffffffu, s1, off);
        s2 += __shfl_xor_sync(0xffffffffu, s2, off);
        s3 += __shfl_xor_sync(0xffffffffu, s3, off);
        s4 += __shfl_xor_sync(0xffffffffu, s4, off);
    }
    if (active && lane == 0) {
        out_wsum[r]      = s0;
        out_depth[r]     = s1;
        out_image[r*3+0] = s2;
        out_image[r*3+1] = s3;
        out_image[r*3+2] = s4;
    }
}

extern "C" void kernel_launch(void* const* d_in, const int* in_sizes, int n_in,
                              void* d_out, int out_size) {
    const float* rays_o  = (const float*)d_in[0];
    const float* rays_d  = (const float*)d_in[1];
    const float* W1      = (const float*)d_in[2];
    const float* W2      = (const float*)d_in[3];
    const float* b1      = (const float*)d_in[4];
    const float* w_sigma = (const float*)d_in[5];
    const float* W_color = (const float*)d_in[6];

    const int BN = in_sizes[0] / 3;   // B*N rays

    float* out = (float*)d_out;
    // output layout: image [BN,3], depth [BN], weights [BN,NS], weights_sum [BN]
    float* out_image   = out;
    float* out_depth   = out + (size_t)BN * 3;
    float* out_weights = out + (size_t)BN * 4;
    float* out_wsum    = out + (size_t)BN * 4 + (size_t)BN * NS;

    const int blocks = (BN + RPB - 1) / RPB;
    nerf_render_kernel<<<blocks, THREADS>>>(rays_o, rays_d, W1, W2, b1, w_sigma,
                                            W_color, out_image, out_depth,
                                            out_weights, out_wsum, BN);
}